// round 12
// baseline (speedup 1.0000x reference)
#include <cuda_runtime.h>

#define B 32
#define M 32
#define C 1024
#define R 28
#define INV_R2 (1.0f / (R * R))

#define IMGS_PER_BLK 8
#define ROWS_PER_BLK (IMGS_PER_BLK * R)          // 224
#define F4_PER_BLK (ROWS_PER_BLK * R / 4)        // 1568
#define THREADS 224
#define F4_PER_THREAD (F4_PER_BLK / THREADS)     // 7
#define F4_PER_WARP (F4_PER_THREAD * 32)         // 224
#define BLKS_PER_B (C / IMGS_PER_BLK)            // 128

// Scratch (allocation-free rule: __device__ global)
__device__ float g_col[B * M * R];   // column sums of Masks: (B, M, R)

// ---------------------------------------------------------------------------
// Kernel 1 (primary): col[b,m,j] = sum_i Masks[b,m,i,j].
// Triggers PDL completion immediately so the fused grid launches while this
// runs. 28672 threads, __ldcs, MLP=28, coalesced across j.
// ---------------------------------------------------------------------------
__global__ void reduce_M_kernel(const float* __restrict__ Mk) {
    cudaTriggerProgrammaticLaunchCompletion();
    int tid = blockIdx.x * blockDim.x + threadIdx.x;
    if (tid >= B * M * R) return;
    int j  = tid % R;
    int bm = tid / R;
    const float* p = Mk + (size_t)bm * R * R + j;
    float s = 0.0f;
#pragma unroll
    for (int i = 0; i < R; i++) s += __ldcs(p + i * R);
    g_col[tid] = s;
}

// ---------------------------------------------------------------------------
// Kernel 2 (secondary, PDL): WARP-DECOUPLED version of the R9 core.
// Warp w owns the contiguous f4 span [224w, 224w+224) = tile rows
// [32w, 32w+32). Load (7 x LDG.128, 512B contiguous per LDG), partial hsum
// STS, and per-lane rowsum all complete under __syncwarp() only — warps no
// longer phase-lock on each other's DRAM latency. ONE block barrier remains,
// merged with col_s staging behind the HW grid-dependency sync.
//  - partial read: lane l reads [7l..7l+6]+224w; 7l mod 32 is a lane
//    permutation per k -> conflict-free.
//  - rowsum[tid] semantics identical to R9 (row t = f4 [7t, 7t+7)).
// ---------------------------------------------------------------------------
__global__ void fused_rowsum_einsum_kernel(const float* __restrict__ F,
                                           float* __restrict__ out) {
    __shared__ float partial[F4_PER_BLK];     // 1568 floats = 6.3 KB
    __shared__ float rowsum[ROWS_PER_BLK];    // 224 floats: [c_local*28 + i]
    __shared__ float col_s[M * R];            // 896 floats: [m*28 + r]

    const int tid  = threadIdx.x;
    const int w    = tid >> 5;                // warp 0..6
    const int lane = tid & 31;
    const int blk  = blockIdx.x;
    const int b    = blk / BLKS_PER_B;

    // Warp-contiguous F load batch: 7 coalesced LDG.128, all in flight.
    const float4* src = reinterpret_cast<const float4*>(F)
                      + (size_t)blk * F4_PER_BLK + w * F4_PER_WARP;
    float4 v[F4_PER_THREAD];
#pragma unroll
    for (int k = 0; k < F4_PER_THREAD; k++) v[k] = src[k * 32 + lane];

    // f4 horizontal sums -> scalar partials within the warp's span.
    float* pbase = partial + w * F4_PER_WARP;
#pragma unroll
    for (int k = 0; k < F4_PER_THREAD; k++)
        pbase[k * 32 + lane] = (v[k].x + v[k].y) + (v[k].z + v[k].w);
    __syncwarp();

    // Per-lane row sum: lane l owns tile row 32w+l = local f4 [7l, 7l+7).
    {
        float s = 0.0f;
#pragma unroll
        for (int k = 0; k < F4_PER_THREAD; k++) s += pbase[7 * lane + k];
        rowsum[w * 32 + lane] = s;
    }

    // HW wait for reduce_M (no spin), stage col[b] (L2-hot), then the single
    // block-wide barrier covering both rowsum[] and col_s[].
    cudaGridDependencySynchronize();
    {
        const float* cp = g_col + b * (M * R);
#pragma unroll
        for (int k = 0; k < 4; k++)
            col_s[k * THREADS + tid] = cp[k * THREADS + tid];
    }
    __syncthreads();

    // Einsum tail: 256 outputs = 32 m x 8 c_local.
    const int c0 = (blk % BLKS_PER_B) * IMGS_PER_BLK;
    for (int o = tid; o < M * IMGS_PER_BLK; o += THREADS) {
        int m  = o / IMGS_PER_BLK;
        int cl = o % IMGS_PER_BLK;
        float acc = 0.0f;
#pragma unroll
        for (int r = 0; r < R; r++)
            acc += col_s[m * R + r] * rowsum[cl * R + r];
        out[((size_t)b * M + m) * C + c0 + cl] = acc * INV_R2;
    }
}

extern "C" void kernel_launch(void* const* d_in, const int* in_sizes, int n_in,
                              void* d_out, int out_size) {
    const float* F  = (const float*)d_in[0];  // (B, C, R, R)
    const float* Mk = (const float*)d_in[1];  // (B, M, R, R)
    float* out = (float*)d_out;               // (B, M, C)

    // Primary: plain launch on the capture stream.
    {
        int n = B * M * R;  // 28672
        reduce_M_kernel<<<(n + 255) / 256, 256>>>(Mk);
    }

    // Secondary: PDL launch — starts as soon as the primary triggers.
    {
        cudaLaunchConfig_t cfg = {};
        cfg.gridDim  = dim3((B * C) / IMGS_PER_BLK);   // 4096
        cfg.blockDim = dim3(THREADS);
        cfg.dynamicSmemBytes = 0;
        cfg.stream = 0;
        cudaLaunchAttribute attr[1];
        attr[0].id = cudaLaunchAttributeProgrammaticStreamSerialization;
        attr[0].val.programmaticStreamSerializationAllowed = 1;
        cfg.attrs = attr;
        cfg.numAttrs = 1;
        cudaLaunchKernelEx(&cfg, fused_rowsum_einsum_kernel, F, out);
    }
}

// round 13
// speedup vs baseline: 1.0124x; 1.0124x over previous
#include <cuda_runtime.h>
#include <cstdint>

#define B 32
#define M 32
#define C 1024
#define R 28
#define INV_R2 (1.0f / (R * R))

#define IMGS_PER_BLK 8
#define ROWS_PER_BLK (IMGS_PER_BLK * R)          // 224
#define FLOATS_PER_BLK (ROWS_PER_BLK * R)        // 6272
#define TILE_BYTES (FLOATS_PER_BLK * 4)          // 25088
#define THREADS 224
#define BLKS_PER_B (C / IMGS_PER_BLK)            // 128

// Scratch (allocation-free rule: __device__ global)
__device__ float g_col[B * M * R];   // column sums of Masks: (B, M, R)

__device__ __forceinline__ uint32_t smem_u32(const void* p) {
    uint32_t a;
    asm("{ .reg .u64 t; cvta.to.shared.u64 t, %1; cvt.u32.u64 %0, t; }"
        : "=r"(a) : "l"(p));
    return a;
}

// ---------------------------------------------------------------------------
// Kernel 1 (primary): col[b,m,j] = sum_i Masks[b,m,i,j].
// PDL-triggers immediately; 28672 threads, __ldcs, MLP=28.
// ---------------------------------------------------------------------------
__global__ void reduce_M_kernel(const float* __restrict__ Mk) {
    cudaTriggerProgrammaticLaunchCompletion();
    int tid = blockIdx.x * blockDim.x + threadIdx.x;
    if (tid >= B * M * R) return;
    int j  = tid % R;
    int bm = tid / R;
    const float* p = Mk + (size_t)bm * R * R + j;
    float s = 0.0f;
#pragma unroll
    for (int i = 0; i < R; i++) s += __ldcs(p + i * R);
    g_col[tid] = s;
}

// ---------------------------------------------------------------------------
// Kernel 2 (secondary, PDL): TMA-bulk version. One cp.async.bulk moves the
// whole 25088B tile global->smem through the copy engine — zero data regs,
// zero L1tex wavefront pressure, zero issue-slot cost. 7 blocks/SM x 25KB =
// 175KB in flight per SM, HW-queued. While the bulk copy flies, the block
// does the PDL sync + col_s staging. After the mbarrier flips: the proven
// conflict-free rowsum (7x LDS.128, bank-group permutation) and einsum tail.
// ---------------------------------------------------------------------------
__global__ void fused_rowsum_einsum_kernel(const float* __restrict__ F,
                                           float* __restrict__ out) {
    __shared__ alignas(16) float tile[FLOATS_PER_BLK];  // 25088 B
    __shared__ float rowsum[ROWS_PER_BLK];              // 224 floats
    __shared__ float col_s[M * R];                      // 896 floats
    __shared__ alignas(8) uint64_t mbar;

    const int tid = threadIdx.x;
    const int blk = blockIdx.x;
    const int b   = blk / BLKS_PER_B;
    const uint32_t mbar_a = smem_u32(&mbar);

    if (tid == 0) {
        asm volatile("mbarrier.init.shared.b64 [%0], 1;" :: "r"(mbar_a) : "memory");
    }
    __syncthreads();

    if (tid == 0) {
        asm volatile("mbarrier.arrive.expect_tx.shared.b64 _, [%0], %1;"
                     :: "r"(mbar_a), "r"((uint32_t)TILE_BYTES) : "memory");
        const void* src = (const char*)F + (size_t)blk * TILE_BYTES;
        asm volatile(
            "cp.async.bulk.shared::cluster.global.mbarrier::complete_tx::bytes "
            "[%0], [%1], %2, [%3];"
            :: "r"(smem_u32(tile)), "l"(src), "r"((uint32_t)TILE_BYTES), "r"(mbar_a)
            : "memory");
    }

    // Overlap the bulk copy: HW wait for reduce_M, stage col[b] (L2-hot).
    cudaGridDependencySynchronize();
    {
        const float* cp = g_col + b * (M * R);
#pragma unroll
        for (int k = 0; k < 4; k++)
            col_s[k * THREADS + tid] = cp[k * THREADS + tid];
    }

    // Wait for the tile (acquire orders the async-proxy writes before LDS).
    {
        uint32_t done;
        asm volatile(
            "{\n\t.reg .pred p;\n\t"
            "mbarrier.try_wait.parity.acquire.cta.shared::cta.b64 p, [%1], 0;\n\t"
            "selp.b32 %0, 1, 0, p;\n\t}"
            : "=r"(done) : "r"(mbar_a) : "memory");
        if (!done) {
            asm volatile(
                "{\n\t.reg .pred P1;\n\t"
                "WL_%=:\n\t"
                "mbarrier.try_wait.parity.acquire.cta.shared::cta.b64 P1, [%0], 0, 0x989680;\n\t"
                "@P1 bra.uni WD_%=;\n\t"
                "bra.uni WL_%=;\n\t"
                "WD_%=:\n\t}"
                :: "r"(mbar_a) : "memory");
        }
    }

    // Row sums: thread t sums row t (7 x LDS.128; f4-bank-group 7t mod 8 is
    // a permutation per 8-lane phase -> conflict-free).
    {
        const float4* rp = reinterpret_cast<const float4*>(tile) + tid * (R / 4);
        float s = 0.0f;
#pragma unroll
        for (int k = 0; k < R / 4; k++) {
            float4 w = rp[k];
            s += (w.x + w.y) + (w.z + w.w);
        }
        rowsum[tid] = s;
    }
    __syncthreads();

    // Einsum tail: 256 outputs = 32 m x 8 c_local.
    const int c0 = (blk % BLKS_PER_B) * IMGS_PER_BLK;
    for (int o = tid; o < M * IMGS_PER_BLK; o += THREADS) {
        int m  = o / IMGS_PER_BLK;
        int cl = o % IMGS_PER_BLK;
        float acc = 0.0f;
#pragma unroll
        for (int r = 0; r < R; r++)
            acc += col_s[m * R + r] * rowsum[cl * R + r];
        out[((size_t)b * M + m) * C + c0 + cl] = acc * INV_R2;
    }
}

extern "C" void kernel_launch(void* const* d_in, const int* in_sizes, int n_in,
                              void* d_out, int out_size) {
    const float* F  = (const float*)d_in[0];  // (B, C, R, R)
    const float* Mk = (const float*)d_in[1];  // (B, M, R, R)
    float* out = (float*)d_out;               // (B, M, C)

    // Primary: plain launch on the capture stream.
    {
        int n = B * M * R;  // 28672
        reduce_M_kernel<<<(n + 255) / 256, 256>>>(Mk);
    }

    // Secondary: PDL launch — starts as soon as the primary triggers.
    {
        cudaLaunchConfig_t cfg = {};
        cfg.gridDim  = dim3((B * C) / IMGS_PER_BLK);   // 4096
        cfg.blockDim = dim3(THREADS);
        cfg.dynamicSmemBytes = 0;
        cfg.stream = 0;
        cudaLaunchAttribute attr[1];
        attr[0].id = cudaLaunchAttributeProgrammaticStreamSerialization;
        attr[0].val.programmaticStreamSerializationAllowed = 1;
        cfg.attrs = attr;
        cfg.numAttrs = 1;
        cudaLaunchKernelEx(&cfg, fused_rowsum_einsum_kernel, F, out);
    }
}

// round 14
// speedup vs baseline: 1.1099x; 1.0964x over previous
#include <cuda_runtime.h>
#include <cstdint>

#define B 32
#define M 32
#define C 1024
#define R 28
#define INV_R2 (1.0f / (R * R))

#define IMGS 8
#define ROWS (IMGS * R)                  // 224
#define TILE_FLOATS (ROWS * R)           // 6272
#define TILE_BYTES (TILE_FLOATS * 4)     // 25088
#define THREADS 224
#define BLKS_PER_B (C / IMGS)            // 128
#define NTILES (B * C / IMGS)            // 4096
#define GRID 592                         // 4 blocks/SM x 148 (fully resident)

// Dynamic smem layout (bytes)
#define OFF_T0   0
#define OFF_T1   TILE_BYTES              // 25088
#define OFF_COL  (2 * TILE_BYTES)        // 50176 : col_s, 896 floats
#define OFF_ROW  (OFF_COL + 3584)        // 53760 : rowsum, 224 floats
#define OFF_MBAR (OFF_ROW + 896)         // 54656 : 2 x u64 mbarriers
#define SMEM_TOTAL (OFF_MBAR + 16)       // 54672

__device__ float g_col[B * M * R];

__device__ __forceinline__ uint32_t smem_u32(const void* p) {
    uint32_t a;
    asm("{ .reg .u64 t; cvta.to.shared.u64 t, %1; cvt.u32.u64 %0, t; }"
        : "=r"(a) : "l"(p));
    return a;
}

__device__ __forceinline__ void mbar_wait(uint32_t mbar_a, uint32_t parity) {
    uint32_t done;
    asm volatile(
        "{\n\t.reg .pred p;\n\t"
        "mbarrier.try_wait.parity.acquire.cta.shared::cta.b64 p, [%1], %2;\n\t"
        "selp.b32 %0, 1, 0, p;\n\t}"
        : "=r"(done) : "r"(mbar_a), "r"(parity) : "memory");
    if (!done) {
        asm volatile(
            "{\n\t.reg .pred P1;\n\t"
            "WL_%=:\n\t"
            "mbarrier.try_wait.parity.acquire.cta.shared::cta.b64 P1, [%0], %1, 0x989680;\n\t"
            "@P1 bra.uni WD_%=;\n\t"
            "bra.uni WL_%=;\n\t"
            "WD_%=:\n\t}"
            :: "r"(mbar_a), "r"(parity) : "memory");
    }
}

// ---------------------------------------------------------------------------
// Kernel 1 (primary): col[b,m,j] = sum_i Masks[b,m,i,j]. PDL-triggers
// immediately; 28672 threads, __ldcs, MLP=28.
// ---------------------------------------------------------------------------
__global__ void reduce_M_kernel(const float* __restrict__ Mk) {
    cudaTriggerProgrammaticLaunchCompletion();
    int tid = blockIdx.x * blockDim.x + threadIdx.x;
    if (tid >= B * M * R) return;
    int j  = tid % R;
    int bm = tid / R;
    const float* p = Mk + (size_t)bm * R * R + j;
    float s = 0.0f;
#pragma unroll
    for (int i = 0; i < R; i++) s += __ldcs(p + i * R);
    g_col[tid] = s;
}

// ---------------------------------------------------------------------------
// Kernel 2 (secondary, PDL): PERSISTENT + TMA DOUBLE-BUFFER.
// Each of 592 blocks owns tiles {bid, bid+592, ...} (~7 tiles). At iteration
// i it first issues the bulk copy for tile i+1 into the alternate buffer,
// THEN waits/computes tile i — so a 25KB copy is in flight during compute,
// killing the wave-synchronized load/compute phase correlation that pinned
// all prior versions at ~60-66% DRAM. Buffer reuse is safe: the copy into
// buf s at iter i+1 is issued after the __syncthreads() following rowsum's
// reads of buf s at iter i-1.
// ---------------------------------------------------------------------------
__global__ void persistent_fused_kernel(const float* __restrict__ F,
                                        float* __restrict__ out) {
    extern __shared__ char smem[];
    float* tiles[2] = { (float*)(smem + OFF_T0), (float*)(smem + OFF_T1) };
    float* col_s    = (float*)(smem + OFF_COL);   // [m*28 + r]
    float* rowsum   = (float*)(smem + OFF_ROW);   // [c_local*28 + i]
    uint64_t* mbar  = (uint64_t*)(smem + OFF_MBAR);

    const int tid = threadIdx.x;
    const int bid = blockIdx.x;
    const uint32_t mb[2] = { smem_u32(&mbar[0]), smem_u32(&mbar[1]) };
    const uint32_t td[2] = { smem_u32(tiles[0]), smem_u32(tiles[1]) };

    if (tid == 0) {
        asm volatile("mbarrier.init.shared.b64 [%0], 1;" :: "r"(mb[0]) : "memory");
        asm volatile("mbarrier.init.shared.b64 [%0], 1;" :: "r"(mb[1]) : "memory");
    }
    __syncthreads();

    // Prologue: copy for first tile into buf 0.
    if (bid < NTILES && tid == 0) {
        asm volatile("mbarrier.arrive.expect_tx.shared.b64 _, [%0], %1;"
                     :: "r"(mb[0]), "r"((uint32_t)TILE_BYTES) : "memory");
        asm volatile(
            "cp.async.bulk.shared::cluster.global.mbarrier::complete_tx::bytes "
            "[%0], [%1], %2, [%3];"
            :: "r"(td[0]), "l"((const char*)F + (size_t)bid * TILE_BYTES),
               "r"((uint32_t)TILE_BYTES), "r"(mb[0]) : "memory");
    }

    // HW wait for reduce_M before any g_col read (copies above don't touch it).
    cudaGridDependencySynchronize();

    int it = 0;
    for (int t = bid; t < NTILES; t += GRID, ++it) {
        const int stage = it & 1;
        const uint32_t parity = (it >> 1) & 1;

        // Prefetch tile t+GRID into the alternate buffer (in flight during
        // this tile's wait + compute).
        const int tn = t + GRID;
        if (tn < NTILES && tid == 0) {
            const int ns = stage ^ 1;
            asm volatile("mbarrier.arrive.expect_tx.shared.b64 _, [%0], %1;"
                         :: "r"(mb[ns]), "r"((uint32_t)TILE_BYTES) : "memory");
            asm volatile(
                "cp.async.bulk.shared::cluster.global.mbarrier::complete_tx::bytes "
                "[%0], [%1], %2, [%3];"
                :: "r"(td[ns]), "l"((const char*)F + (size_t)tn * TILE_BYTES),
                   "r"((uint32_t)TILE_BYTES), "r"(mb[ns]) : "memory");
        }

        // Stage col[b] for this tile (L2-hot; hidden under the copy wait).
        {
            const float* cp = g_col + (t / BLKS_PER_B) * (M * R);
#pragma unroll
            for (int k = 0; k < 4; k++)
                col_s[k * THREADS + tid] = cp[k * THREADS + tid];
        }

        // Wait for this tile's data (acquire orders async-proxy writes).
        mbar_wait(mb[stage], parity);

        // Row sums: thread tid sums row tid (7 x LDS.128; f4-bank-group
        // 7t mod 8 is a permutation per 8-lane phase -> conflict-free).
        {
            const float4* rp = reinterpret_cast<const float4*>(tiles[stage]) + tid * (R / 4);
            float s = 0.0f;
#pragma unroll
            for (int k = 0; k < R / 4; k++) {
                float4 w = rp[k];
                s += (w.x + w.y) + (w.z + w.w);
            }
            rowsum[tid] = s;
        }
        __syncthreads();   // rowsum + col_s visible; tile[stage] reads done

        // Einsum tail: 256 outputs = 32 m x 8 c_local.
        const int b  = t / BLKS_PER_B;
        const int c0 = (t % BLKS_PER_B) * IMGS;
        for (int o = tid; o < M * IMGS; o += THREADS) {
            int m  = o / IMGS;
            int cl = o % IMGS;
            float acc = 0.0f;
#pragma unroll
            for (int r = 0; r < R; r++)
                acc += col_s[m * R + r] * rowsum[cl * R + r];
            out[((size_t)b * M + m) * C + c0 + cl] = acc * INV_R2;
        }
        __syncthreads();   // einsum's col_s/rowsum reads done before reuse
    }
}

extern "C" void kernel_launch(void* const* d_in, const int* in_sizes, int n_in,
                              void* d_out, int out_size) {
    const float* F  = (const float*)d_in[0];  // (B, C, R, R)
    const float* Mk = (const float*)d_in[1];  // (B, M, R, R)
    float* out = (float*)d_out;               // (B, M, C)

    static int attr_set = 0;
    if (!attr_set) {
        cudaFuncSetAttribute(persistent_fused_kernel,
                             cudaFuncAttributeMaxDynamicSharedMemorySize, SMEM_TOTAL);
        attr_set = 1;
    }

    // Primary: plain launch on the capture stream.
    {
        int n = B * M * R;  // 28672
        reduce_M_kernel<<<(n + 255) / 256, 256>>>(Mk);
    }

    // Secondary: PDL launch — starts as soon as the primary triggers.
    {
        cudaLaunchConfig_t cfg = {};
        cfg.gridDim  = dim3(GRID);
        cfg.blockDim = dim3(THREADS);
        cfg.dynamicSmemBytes = SMEM_TOTAL;
        cfg.stream = 0;
        cudaLaunchAttribute attr[1];
        attr[0].id = cudaLaunchAttributeProgrammaticStreamSerialization;
        attr[0].val.programmaticStreamSerializationAllowed = 1;
        cfg.attrs = attr;
        cfg.numAttrs = 1;
        cudaLaunchKernelEx(&cfg, persistent_fused_kernel, F, out);
    }
}